// round 12
// baseline (speedup 1.0000x reference)
#include <cuda_runtime.h>
#include <cuda_bf16.h>
#include <math_constants.h>

// SupPixPool: out[b][c][k] = max over pixels p with spx[b][p]==k of img[b][c][p]
// B=4, C=64, H=W=512 (HW=262144), K=1024. out viewed as [256 channels][1024].
//
// R12: balanced linearized decomposition. R11 (one CTA per channel, grid 256)
// ran at 256/296 = 86.5% SM-slot utilization (40 SMs half-idle). Now exactly
// 296 CTAs (2/SM, single perfectly-balanced wave); work = 67.1M linearized
// (channel, pixel) items in 296 contiguous 226720-item chunks. A chunk spans
// <=2 channels -> <=2 scatter/merge spans; merges go to global atomicMax
// (out as int accumulator); per-channel tickets trigger in-place decode.
//
// Scatter: RSUB=16 sub-slots (64 KB), slot = k*16 + (lane&15): bank==lane
// within each half-warp, pairwise conflicts only (<=2 wavefronts/ATOMS).
// Bias +128.0f: values positive -> float order == s32 bit order -> single
// atomicMax(int) combine; decode subtracts the bias.

#define HW    262144
#define KSEG  1024
#define BC_TOT 256               // B*C channels
#define NTOT  (BC_TOT * HW)      // 67,108,864 items
#define NCTA  296                // 2 CTAs per SM exactly
#define CHUNK 226720             // ceil(NTOT/NCTA) rounded to mult of 4
#define NTHR  1024
#define RSUB  16
#define BIAS  128.0f
#define NEG_INF_BITS 0xFF800000u
#define SLOT_BYTES (KSEG * RSUB * 4)   // 64 KB dynamic smem

__device__ int g_tickets[BC_TOT];

__global__ void __launch_bounds__(256) sp_init_kernel(uint4* __restrict__ out) {
    const uint4 v = make_uint4(NEG_INF_BITS, NEG_INF_BITS, NEG_INF_BITS, NEG_INF_BITS);
    out[blockIdx.x * 256 + threadIdx.x] = v;   // 256 blocks x 256 thr x 16B = 1MB
    if (blockIdx.x == 0 && threadIdx.x < BC_TOT)
        g_tickets[threadIdx.x] = 0;
}

__global__ void __launch_bounds__(NTHR, 2) sp_main_kernel(const float* __restrict__ img,
                                                          const int*   __restrict__ spx,
                                                          int*         __restrict__ out) {
    extern __shared__ int slots[];          // [KSEG * RSUB] = 64 KB
    __shared__ int sh_flag;

    const int tid  = threadIdx.x;
    const int lane = tid & 31;
    const int wid  = tid >> 5;              // 0..31
    const int sub  = lane & 15;

    // Init sub-slots to -inf.
    {
        const uint4 v = make_uint4(NEG_INF_BITS, NEG_INF_BITS, NEG_INF_BITS, NEG_INF_BITS);
        uint4* s4p = reinterpret_cast<uint4*>(slots);
        #pragma unroll
        for (int i = tid; i < KSEG * RSUB / 4; i += NTHR)
            s4p[i] = v;
    }
    __syncthreads();

    const long g0 = (long)blockIdx.x * CHUNK;
    const long g1 = min((long)NTOT, g0 + CHUNK);
    int* laneslot = slots + sub;

    long gs = g0;
    while (gs < g1) {
        const int  bc = (int)(gs / HW);            // channel index (b*64+c)
        const long ce = (long)(bc + 1) * HW;       // channel end (global)
        const long ge = min(g1, ce);
        const int  ls = (int)(gs - (long)bc * HW); // local [ls, le), 4-aligned
        const int  le = (int)(ge - (long)bc * HW);
        const bool more = (ge < g1);

        // ---- scatter this span ----
        {
            const int*   spxb = spx + (bc >> 6) * HW;
            const float* imgb = img + (size_t)bc * HW;
            for (int p = ls + (tid << 2); p < le; p += NTHR * 4) {
                const int4   s = __ldg(reinterpret_cast<const int4*>(spxb + p));
                const float4 v = __ldcs(reinterpret_cast<const float4*>(imgb + p));
                atomicMax(laneslot + s.x * RSUB, __float_as_int(v.x + BIAS));
                atomicMax(laneslot + s.y * RSUB, __float_as_int(v.y + BIAS));
                atomicMax(laneslot + s.z * RSUB, __float_as_int(v.z + BIAS));
                atomicMax(laneslot + s.w * RSUB, __float_as_int(v.w + BIAS));
            }
        }
        __syncthreads();

        // ---- merge: warp w owns segments [w*32, w*32+32); width-16 shfl
        //      butterflies; lane keeps segment wbase+lane -> coalesced atomics.
        int* outg = out + bc * KSEG;
        {
            const int wbase = wid * 32;
            const int hi    = lane >> 4;
            int keep = (int)NEG_INF_BITS;
            #pragma unroll
            for (int i = 0; i < 16; ++i) {
                const int k = wbase + hi * 16 + i;
                int v = slots[k * RSUB + sub];
                if (more)
                    slots[k * RSUB + sub] = (int)NEG_INF_BITS;  // reset for next span
                #pragma unroll
                for (int m = 8; m >= 1; m >>= 1)
                    v = max(v, __shfl_xor_sync(0xFFFFFFFFu, v, m, 16));
                if (sub == i) keep = v;
            }
            atomicMax(&outg[wbase + lane], keep);
        }

        // ---- ticket: last contributor to channel bc decodes it ----
        __threadfence();
        if (tid == 0) {
            const int first = (int)(((long)bc * HW) / CHUNK);
            const int last  = (int)((((long)(bc + 1) * HW) - 1) / CHUNK);
            sh_flag = (atomicAdd(&g_tickets[bc], 1) == (last - first));
        }
        __syncthreads();

        if (sh_flag) {
            const int w = __ldcg(&outg[tid]);
            reinterpret_cast<float*>(outg)[tid] = __int_as_float(w) - BIAS;
        }
        __syncthreads();   // sh_flag / slot resets settled before next span

        gs = ge;
    }
}

extern "C" void kernel_launch(void* const* d_in, const int* in_sizes, int n_in,
                              void* d_out, int out_size) {
    const float* img = (const float*)d_in[0];   // [4, 64, 512, 512] f32
    const int*   spx = (const int*)d_in[1];     // [4, 512, 512] i32

    static int smem_set = 0;
    if (!smem_set) {
        cudaFuncSetAttribute(sp_main_kernel,
                             cudaFuncAttributeMaxDynamicSharedMemorySize, SLOT_BYTES);
        smem_set = 1;
    }

    sp_init_kernel<<<256, 256>>>((uint4*)d_out);
    sp_main_kernel<<<NCTA, NTHR, SLOT_BYTES>>>(img, spx, (int*)d_out);
}

// round 13
// speedup vs baseline: 1.0367x; 1.0367x over previous
#include <cuda_runtime.h>
#include <cuda_bf16.h>
#include <math_constants.h>

// SupPixPool: out[b][c][k] = max over pixels p with spx[b][p]==k of img[b][c][p]
// B=4, C=64, H=W=512 (HW=262144), K=1024. out viewed as [256 channels][1024].
//
// R13: R11's fast body (RSUB=16 sub-slot scatter, static unrolled loops,
// shfl merge) with near-perfect static balance. Work = 2048 tiles of 32K
// pixels (8 tiles/channel), split contiguously over 296 CTAs (exactly
// 2 CTAs/SM x 148 SMs): CTA i owns tiles [i*2048/296, (i+1)*2048/296)
// -> 6-7 contiguous tiles, 98.8% slot utilization, <=2 channels touched
// -> <=2 merge phases. Scatter inner loop is a compile-time 8 iterations.
// Merge -> global atomicMax accumulator; tiny decode kernel subtracts the
// +128.0f bias (bias makes values positive so float order == s32 bit order
// and one atomicMax(int) suffices).

#define HW    262144
#define KSEG  1024
#define BC_TOT 256               // B*C channels
#define NCTA  296
#define TILE  32768              // pixels per tile
#define TPCH  8                  // tiles per channel
#define NTILE (BC_TOT * TPCH)    // 2048
#define NTHR  1024
#define PPT_T (TILE / NTHR)      // 32 pixels/thread/tile -> 8 int4 iters
#define RSUB  16
#define BIAS  128.0f
#define NEG_INF_BITS 0xFF800000u
#define SLOT_BYTES (KSEG * RSUB * 4)   // 64 KB dynamic smem

__global__ void __launch_bounds__(256) sp_init_kernel(uint4* __restrict__ out) {
    const uint4 v = make_uint4(NEG_INF_BITS, NEG_INF_BITS, NEG_INF_BITS, NEG_INF_BITS);
    out[blockIdx.x * 256 + threadIdx.x] = v;   // 256 x 256 x 16B = 1MB
}

__global__ void __launch_bounds__(256) sp_decode_kernel(int* __restrict__ out) {
    const int i = (blockIdx.x * 256 + threadIdx.x) * 4;
    const int4 w = *reinterpret_cast<const int4*>(out + i);
    float4 f;
    f.x = __int_as_float(w.x) - BIAS;
    f.y = __int_as_float(w.y) - BIAS;
    f.z = __int_as_float(w.z) - BIAS;
    f.w = __int_as_float(w.w) - BIAS;
    *reinterpret_cast<float4*>(out + i) = f;
}

__device__ __forceinline__ void merge_channel(const int* __restrict__ slots,
                                              int* __restrict__ out,
                                              int bc, int wid, int lane, int sub) {
    // Warp w owns segments [w*32, w*32+32). Lower/upper 16 lanes reduce
    // segments wbase+i / wbase+16+i via width-16 shfl butterflies; lane
    // keeps segment wbase+lane -> coalesced global atomics.
    const int wbase = wid * 32;
    const int hi    = lane >> 4;
    int keep = (int)NEG_INF_BITS;
    #pragma unroll
    for (int i = 0; i < 16; ++i) {
        const int k = wbase + hi * 16 + i;
        int v = slots[k * RSUB + sub];
        #pragma unroll
        for (int m = 8; m >= 1; m >>= 1)
            v = max(v, __shfl_xor_sync(0xFFFFFFFFu, v, m, 16));
        if (sub == i) keep = v;
    }
    atomicMax(&out[bc * KSEG + wbase + lane], keep);
}

__device__ __forceinline__ void reset_slots(int* __restrict__ slots, int tid) {
    const uint4 v = make_uint4(NEG_INF_BITS, NEG_INF_BITS, NEG_INF_BITS, NEG_INF_BITS);
    uint4* s4p = reinterpret_cast<uint4*>(slots);
    #pragma unroll
    for (int i = tid; i < KSEG * RSUB / 4; i += NTHR)
        s4p[i] = v;
}

__global__ void __launch_bounds__(NTHR, 2) sp_main_kernel(const float* __restrict__ img,
                                                          const int*   __restrict__ spx,
                                                          int*         __restrict__ out) {
    extern __shared__ int slots[];          // [KSEG * RSUB] = 64 KB

    const int tid  = threadIdx.x;
    const int lane = tid & 31;
    const int wid  = tid >> 5;
    const int sub  = lane & 15;

    const int t0 = (int)(((long)blockIdx.x * NTILE) / NCTA);
    const int t1 = (int)(((long)(blockIdx.x + 1) * NTILE) / NCTA);

    reset_slots(slots, tid);
    __syncthreads();

    int* laneslot = slots + sub;
    int cur = t0 >> 3;                      // current channel (t0/TPCH)

    for (int t = t0; t < t1; ++t) {
        const int bc = t >> 3;
        if (bc != cur) {
            __syncthreads();                // all scatters for cur done
            merge_channel(slots, out, cur, wid, lane, sub);
            __syncthreads();                // merge reads done before reset
            reset_slots(slots, tid);
            __syncthreads();                // reset visible before scatter
            cur = bc;
        }

        const int*   spxb = spx + (bc >> 6) * HW + (t & 7) * TILE;
        const float* imgb = img + (size_t)bc * HW + (t & 7) * TILE;

        #pragma unroll 4
        for (int i = 0; i < PPT_T / 4; ++i) {    // 8 static iterations
            const int idx = (i * NTHR + tid) * 4;
            const int4   s = __ldg(reinterpret_cast<const int4*>(spxb + idx));
            const float4 v = __ldcs(reinterpret_cast<const float4*>(imgb + idx));
            atomicMax(laneslot + s.x * RSUB, __float_as_int(v.x + BIAS));
            atomicMax(laneslot + s.y * RSUB, __float_as_int(v.y + BIAS));
            atomicMax(laneslot + s.z * RSUB, __float_as_int(v.z + BIAS));
            atomicMax(laneslot + s.w * RSUB, __float_as_int(v.w + BIAS));
        }
    }

    __syncthreads();
    merge_channel(slots, out, cur, wid, lane, sub);
}

extern "C" void kernel_launch(void* const* d_in, const int* in_sizes, int n_in,
                              void* d_out, int out_size) {
    const float* img = (const float*)d_in[0];   // [4, 64, 512, 512] f32
    const int*   spx = (const int*)d_in[1];     // [4, 512, 512] i32

    static int smem_set = 0;
    if (!smem_set) {
        cudaFuncSetAttribute(sp_main_kernel,
                             cudaFuncAttributeMaxDynamicSharedMemorySize, SLOT_BYTES);
        smem_set = 1;
    }

    sp_init_kernel<<<256, 256>>>((uint4*)d_out);
    sp_main_kernel<<<NCTA, NTHR, SLOT_BYTES>>>(img, spx, (int*)d_out);
    sp_decode_kernel<<<256, 256>>>((int*)d_out);   // 256*256*4 ints = 1MB
}